// round 2
// baseline (speedup 1.0000x reference)
#include <cuda_runtime.h>

// Problem constants
#define B_ 8
#define C_ 128
#define H_ 128
#define W_ 128
#define HW_ (H_*W_)

// Scratch (allocation-free: device globals)
__device__ float g_offsets[(size_t)B_ * 2 * C_ * HW_];   // (B, 2C, H, W)  134MB
__device__ float g_xoff[(size_t)B_ * C_ * HW_];          // (B, C, H, W)    67MB
__device__ float g_y[(size_t)B_ * C_ * HW_];             // conv2+relu out  67MB
__device__ float g_sum[C_];
__device__ float g_sumsq[C_];
__device__ float g_scale[C_];
__device__ float g_shift[C_];

// ---------------------------------------------------------------------------
// 3x3 pad-1 stride-1 conv, implicit GEMM.
// Block: 128 output channels x 128 pixels (one full image row). 256 threads,
// each computes an 8oc x 8px micro-tile. K-loop over input channels in chunks
// of 4. Weights staged to smem as wsm[ic4][k][oc] (padded row 132 to spread
// banks); input rows staged zero-padded so all LDS/STS are aligned float4.
// ---------------------------------------------------------------------------
template<int OC, bool EPI>
__global__ void __launch_bounds__(256, 2)
conv3x3_kernel(const float* __restrict__ in, const float* __restrict__ w,
               const float* __restrict__ bias, float* __restrict__ out)
{
    __shared__ float wsm[4][9][132];   // [ic_sub][k][oc]
    __shared__ float ism[4][3][144];   // [ic_sub][ky][x+4], borders stay 0

    const int tid  = threadIdx.x;
    const int tcol = tid & 15;         // pixel group
    const int trow = tid >> 4;         // oc group
    const int px   = tcol << 3;        // output x base (multiple of 8)
    const int ocb  = blockIdx.y * 128 + trow * 8;
    const int b    = blockIdx.x >> 7;
    const int y    = blockIdx.x & 127;

    // zero ism once: borders (x<0, x>=128 pads) remain zero across all chunks
    for (int i = tid; i < 4 * 3 * 144; i += 256) ((float*)ism)[i] = 0.f;

    float acc[64];
#pragma unroll
    for (int i = 0; i < 64; i++) acc[i] = 0.f;

    const float* inb = in + (size_t)b * C_ * HW_;
    const int oc_tile = blockIdx.y * 128;

    __syncthreads();

    for (int ic0 = 0; ic0 < C_; ic0 += 4) {
        // --- stage weights: 128 oc x 36 floats (4 ic x 9 taps), as float4 + transpose scatter
        for (int t = tid; t < 128 * 9; t += 256) {
            const int oc = t / 9, j = t % 9;
            const float4 v = *(const float4*)(w + ((size_t)(oc_tile + oc) * C_ + ic0) * 9 + j * 4);
#pragma unroll
            for (int u = 0; u < 4; u++) {
                const int flat = j * 4 + u;            // 0..35
                wsm[flat / 9][flat % 9][oc] = (&v.x)[u];
            }
        }
        // --- stage input rows: 4 ic x 3 ky, 128 floats each, zero rows for OOB y
        for (int t = tid; t < 12 * 32; t += 256) {
            const int r = t >> 5, q = t & 31;
            const int di = r / 3, ky = r % 3;
            const int yy = y + ky - 1;
            float4 v = make_float4(0.f, 0.f, 0.f, 0.f);
            if (yy >= 0 && yy < H_)
                v = *(const float4*)(inb + ((size_t)(ic0 + di) * H_ + yy) * W_ + q * 4);
            *(float4*)&ism[di][ky][4 + q * 4] = v;
        }
        __syncthreads();

#pragma unroll
        for (int di = 0; di < 4; di++) {
#pragma unroll
            for (int ky = 0; ky < 3; ky++) {
                float r[16];   // x = px-4 .. px+11 ; used: x = px-1 .. px+8
#pragma unroll
                for (int u = 0; u < 4; u++) {
                    const float4 v = *(const float4*)&ism[di][ky][px + u * 4];
                    r[u * 4 + 0] = v.x; r[u * 4 + 1] = v.y;
                    r[u * 4 + 2] = v.z; r[u * 4 + 3] = v.w;
                }
#pragma unroll
                for (int kx = 0; kx < 3; kx++) {
                    const int k = ky * 3 + kx;
                    const float4 a0 = *(const float4*)&wsm[di][k][trow * 8];
                    const float4 a1 = *(const float4*)&wsm[di][k][trow * 8 + 4];
                    float a[8] = {a0.x, a0.y, a0.z, a0.w, a1.x, a1.y, a1.z, a1.w};
#pragma unroll
                    for (int o = 0; o < 8; o++)
#pragma unroll
                        for (int j = 0; j < 8; j++)
                            acc[o * 8 + j] = fmaf(a[o], r[j + kx + 3], acc[o * 8 + j]);
                }
            }
        }
        __syncthreads();
    }

    const size_t obase = ((size_t)b * OC + ocb) * HW_ + (size_t)y * W_ + px;
    if (!EPI) {
#pragma unroll
        for (int o = 0; o < 8; o++) {
            float4 v0 = make_float4(acc[o*8+0], acc[o*8+1], acc[o*8+2], acc[o*8+3]);
            float4 v1 = make_float4(acc[o*8+4], acc[o*8+5], acc[o*8+6], acc[o*8+7]);
            *(float4*)(out + obase + (size_t)o * HW_)     = v0;
            *(float4*)(out + obase + (size_t)o * HW_ + 4) = v1;
        }
    } else {
#pragma unroll
        for (int o = 0; o < 8; o++) {
            const float bv = bias[ocb + o];
            float vv[8];
            float s = 0.f, ss = 0.f;
#pragma unroll
            for (int j = 0; j < 8; j++) {
                float v = fmaxf(acc[o * 8 + j] + bv, 0.f);
                vv[j] = v; s += v; ss += v * v;
            }
            float4 v0 = make_float4(vv[0], vv[1], vv[2], vv[3]);
            float4 v1 = make_float4(vv[4], vv[5], vv[6], vv[7]);
            *(float4*)(out + obase + (size_t)o * HW_)     = v0;
            *(float4*)(out + obase + (size_t)o * HW_ + 4) = v1;
            // reduce over the 16 pixel-groups (lanes 0-15 / 16-31 of the warp)
#pragma unroll
            for (int off = 8; off; off >>= 1) {
                s  += __shfl_down_sync(0xffffffffu, s,  off, 16);
                ss += __shfl_down_sync(0xffffffffu, ss, off, 16);
            }
            if (tcol == 0) {
                atomicAdd(&g_sum[ocb + o], s);
                atomicAdd(&g_sumsq[ocb + o], ss);
            }
        }
    }
}

// ---------------------------------------------------------------------------
// Deformable bilinear sampling, faithful to the reference's quirky reshape:
// for (b, cc), the contiguous 32768-float block covering offset channels
// 2cc and 2cc+1 is reinterpreted as 16384 (dy, dx) pairs.
// ---------------------------------------------------------------------------
__global__ void deform_kernel(const float* __restrict__ x)
{
    const int i = blockIdx.x;                    // b*128 + cc
    const float*  img = x + (size_t)i * HW_;
    const float2* off = (const float2*)(g_offsets + (size_t)i * 2 * HW_);
    float* o = g_xoff + (size_t)i * HW_;

    for (int j = threadIdx.x; j < HW_; j += blockDim.x) {
        const float2 of = off[j];
        const float yf = (float)(j >> 7);
        const float xf = (float)(j & 127);
        const float yc = fminf(fmaxf(of.x + yf, 0.f), 127.f);
        const float xc = fminf(fmaxf(of.y + xf, 0.f), 127.f);
        const float y0f = floorf(yc), x0f = floorf(xc);
        const int y0 = (int)y0f, x0 = (int)x0f;
        const int y1 = (int)ceilf(yc), x1 = (int)ceilf(xc);
        const float dy = yc - y0f, dx = xc - x0f;
        const float vlt = img[y0 * W_ + x0];
        const float vrb = img[y1 * W_ + x1];
        const float vlb = img[y0 * W_ + x1];
        const float vrt = img[y1 * W_ + x0];
        const float vt = vlt + (vrt - vlt) * dy;
        const float vb = vlb + (vrb - vlb) * dy;
        o[j] = vt + (vb - vt) * dx;
    }
}

__global__ void zero_stats_kernel()
{
    g_sum[threadIdx.x] = 0.f;
    g_sumsq[threadIdx.x] = 0.f;
}

__global__ void bn_finalize_kernel(const float* __restrict__ gamma,
                                   const float* __restrict__ beta)
{
    const int c = threadIdx.x;
    const float n = (float)(B_ * HW_);
    const float mean = g_sum[c] / n;
    const float var  = g_sumsq[c] / n - mean * mean;
    const float inv  = rsqrtf(var + 1e-5f);
    const float sc   = inv * gamma[c];
    g_scale[c] = sc;
    g_shift[c] = beta[c] - mean * sc;
}

__global__ void normalize_kernel(float* __restrict__ out)
{
    const int i4 = blockIdx.x * blockDim.x + threadIdx.x;   // float4 index
    const int c = (i4 >> 12) & 127;                          // (4*i4 / 16384) % 128
    const float sc = g_scale[c], sh = g_shift[c];
    float4 v = ((const float4*)g_y)[i4];
    v.x = v.x * sc + sh;
    v.y = v.y * sc + sh;
    v.z = v.z * sc + sh;
    v.w = v.w * sc + sh;
    ((float4*)out)[i4] = v;
}

// ---------------------------------------------------------------------------
extern "C" void kernel_launch(void* const* d_in, const int* in_sizes, int n_in,
                              void* d_out, int out_size)
{
    const float* x      = (const float*)d_in[0];   // (8,128,128,128)
    const float* w_off  = (const float*)d_in[1];   // (256,128,3,3)
    const float* w_conv = (const float*)d_in[2];   // (128,128,3,3)
    const float* b_conv = (const float*)d_in[3];   // (128,)
    const float* gamma  = (const float*)d_in[4];   // (128,)
    const float* beta   = (const float*)d_in[5];   // (128,)
    float* out = (float*)d_out;

    void *p_off, *p_xoff, *p_y;
    cudaGetSymbolAddress(&p_off,  g_offsets);
    cudaGetSymbolAddress(&p_xoff, g_xoff);
    cudaGetSymbolAddress(&p_y,    g_y);

    zero_stats_kernel<<<1, 128>>>();

    // conv1: x -> offsets  (OC=256)
    conv3x3_kernel<256, false><<<dim3(B_ * H_, 2), 256>>>(x, w_off, nullptr, (float*)p_off);

    // deformable sampling: x, offsets -> x_off
    deform_kernel<<<B_ * C_, 256>>>(x);

    // conv2 + bias + relu + BN partial sums  (OC=128)
    conv3x3_kernel<128, true><<<dim3(B_ * H_, 1), 256>>>((const float*)p_xoff, w_conv,
                                                         b_conv, (float*)p_y);

    bn_finalize_kernel<<<1, 128>>>(gamma, beta);

    // normalize: (y - mean)*invstd*gamma + beta -> d_out
    normalize_kernel<<<(B_ * C_ * HW_ / 4) / 256, 256>>>(out);
}

// round 3
// speedup vs baseline: 1.0040x; 1.0040x over previous
#include <cuda_runtime.h>

// Problem constants
#define B_ 8
#define C_ 128
#define H_ 128
#define W_ 128
#define HW_ (H_*W_)

// Scratch (allocation-free: device globals)
__device__ float g_offsets[(size_t)B_ * 2 * C_ * HW_];   // (B, 2C, H, W)  134MB
__device__ float g_xoff[(size_t)B_ * C_ * HW_];          // (B, C, H, W)    67MB
__device__ float g_y[(size_t)B_ * C_ * HW_];             // conv2+relu out  67MB
__device__ float g_sum[C_];
__device__ float g_sumsq[C_];
__device__ float g_scale[C_];
__device__ float g_shift[C_];

// ---------------------------------------------------------------------------
// 3x3 pad-1 stride-1 conv, implicit GEMM.
// Block: 128 output channels x 128 pixels (one full image row). 256 threads,
// each computes an 8oc x 8px micro-tile. K-loop over input channels in chunks
// of 4. Weights staged to smem as wsm[ic4][k][oc] (padded row 132 to spread
// banks); input rows staged zero-padded so all LDS/STS are aligned float4.
// ---------------------------------------------------------------------------
template<int OC, bool EPI>
__global__ void __launch_bounds__(256, 2)
conv3x3_kernel(const float* __restrict__ in, const float* __restrict__ w,
               const float* __restrict__ bias, float* __restrict__ out)
{
    __shared__ float wsm[4][9][132];   // [ic_sub][k][oc]
    __shared__ float ism[4][3][144];   // [ic_sub][ky][x+4], borders stay 0

    const int tid  = threadIdx.x;
    const int tcol = tid & 15;         // pixel group
    const int trow = tid >> 4;         // oc group
    const int px   = tcol << 3;        // output x base (multiple of 8)
    const int ocb  = blockIdx.y * 128 + trow * 8;
    const int b    = blockIdx.x >> 7;
    const int y    = blockIdx.x & 127;

    // zero ism once: borders (x<0, x>=128 pads) remain zero across all chunks
    for (int i = tid; i < 4 * 3 * 144; i += 256) ((float*)ism)[i] = 0.f;

    float acc[64];
#pragma unroll
    for (int i = 0; i < 64; i++) acc[i] = 0.f;

    const float* inb = in + (size_t)b * C_ * HW_;
    const int oc_tile = blockIdx.y * 128;

    __syncthreads();

    for (int ic0 = 0; ic0 < C_; ic0 += 4) {
        // --- stage weights: 128 oc x 36 floats (4 ic x 9 taps), as float4 + transpose scatter
        for (int t = tid; t < 128 * 9; t += 256) {
            const int oc = t / 9, j = t % 9;
            const float4 v = *(const float4*)(w + ((size_t)(oc_tile + oc) * C_ + ic0) * 9 + j * 4);
#pragma unroll
            for (int u = 0; u < 4; u++) {
                const int flat = j * 4 + u;            // 0..35
                wsm[flat / 9][flat % 9][oc] = (&v.x)[u];
            }
        }
        // --- stage input rows: 4 ic x 3 ky, 128 floats each, zero rows for OOB y
        for (int t = tid; t < 12 * 32; t += 256) {
            const int r = t >> 5, q = t & 31;
            const int di = r / 3, ky = r % 3;
            const int yy = y + ky - 1;
            float4 v = make_float4(0.f, 0.f, 0.f, 0.f);
            if (yy >= 0 && yy < H_)
                v = *(const float4*)(inb + ((size_t)(ic0 + di) * H_ + yy) * W_ + q * 4);
            *(float4*)&ism[di][ky][4 + q * 4] = v;
        }
        __syncthreads();

#pragma unroll
        for (int di = 0; di < 4; di++) {
#pragma unroll
            for (int ky = 0; ky < 3; ky++) {
                float r[16];   // x = px-4 .. px+11 ; used: x = px-1 .. px+8
#pragma unroll
                for (int u = 0; u < 4; u++) {
                    const float4 v = *(const float4*)&ism[di][ky][px + u * 4];
                    r[u * 4 + 0] = v.x; r[u * 4 + 1] = v.y;
                    r[u * 4 + 2] = v.z; r[u * 4 + 3] = v.w;
                }
#pragma unroll
                for (int kx = 0; kx < 3; kx++) {
                    const int k = ky * 3 + kx;
                    const float4 a0 = *(const float4*)&wsm[di][k][trow * 8];
                    const float4 a1 = *(const float4*)&wsm[di][k][trow * 8 + 4];
                    float a[8] = {a0.x, a0.y, a0.z, a0.w, a1.x, a1.y, a1.z, a1.w};
#pragma unroll
                    for (int o = 0; o < 8; o++)
#pragma unroll
                        for (int j = 0; j < 8; j++)
                            acc[o * 8 + j] = fmaf(a[o], r[j + kx + 3], acc[o * 8 + j]);
                }
            }
        }
        __syncthreads();
    }

    const size_t obase = ((size_t)b * OC + ocb) * HW_ + (size_t)y * W_ + px;
    if (!EPI) {
#pragma unroll
        for (int o = 0; o < 8; o++) {
            float4 v0 = make_float4(acc[o*8+0], acc[o*8+1], acc[o*8+2], acc[o*8+3]);
            float4 v1 = make_float4(acc[o*8+4], acc[o*8+5], acc[o*8+6], acc[o*8+7]);
            *(float4*)(out + obase + (size_t)o * HW_)     = v0;
            *(float4*)(out + obase + (size_t)o * HW_ + 4) = v1;
        }
    } else {
#pragma unroll
        for (int o = 0; o < 8; o++) {
            const float bv = bias[ocb + o];
            float vv[8];
            float s = 0.f, ss = 0.f;
#pragma unroll
            for (int j = 0; j < 8; j++) {
                float v = fmaxf(acc[o * 8 + j] + bv, 0.f);
                vv[j] = v; s += v; ss += v * v;
            }
            float4 v0 = make_float4(vv[0], vv[1], vv[2], vv[3]);
            float4 v1 = make_float4(vv[4], vv[5], vv[6], vv[7]);
            *(float4*)(out + obase + (size_t)o * HW_)     = v0;
            *(float4*)(out + obase + (size_t)o * HW_ + 4) = v1;
            // reduce over the 16 pixel-groups (lanes 0-15 / 16-31 of the warp)
#pragma unroll
            for (int off = 8; off; off >>= 1) {
                s  += __shfl_down_sync(0xffffffffu, s,  off, 16);
                ss += __shfl_down_sync(0xffffffffu, ss, off, 16);
            }
            if (tcol == 0) {
                atomicAdd(&g_sum[ocb + o], s);
                atomicAdd(&g_sumsq[ocb + o], ss);
            }
        }
    }
}

// ---------------------------------------------------------------------------
// Deformable bilinear sampling, faithful to the reference's quirky reshape:
// for (b, cc), the contiguous 32768-float block covering offset channels
// 2cc and 2cc+1 is reinterpreted as 16384 (dy, dx) pairs.
// ---------------------------------------------------------------------------
__global__ void deform_kernel(const float* __restrict__ x)
{
    const int i = blockIdx.x;                    // b*128 + cc
    const float*  img = x + (size_t)i * HW_;
    const float2* off = (const float2*)(g_offsets + (size_t)i * 2 * HW_);
    float* o = g_xoff + (size_t)i * HW_;

    for (int j = threadIdx.x; j < HW_; j += blockDim.x) {
        const float2 of = off[j];
        const float yf = (float)(j >> 7);
        const float xf = (float)(j & 127);
        const float yc = fminf(fmaxf(of.x + yf, 0.f), 127.f);
        const float xc = fminf(fmaxf(of.y + xf, 0.f), 127.f);
        const float y0f = floorf(yc), x0f = floorf(xc);
        const int y0 = (int)y0f, x0 = (int)x0f;
        const int y1 = (int)ceilf(yc), x1 = (int)ceilf(xc);
        const float dy = yc - y0f, dx = xc - x0f;
        const float vlt = img[y0 * W_ + x0];
        const float vrb = img[y1 * W_ + x1];
        const float vlb = img[y0 * W_ + x1];
        const float vrt = img[y1 * W_ + x0];
        const float vt = vlt + (vrt - vlt) * dy;
        const float vb = vlb + (vrb - vlb) * dy;
        o[j] = vt + (vb - vt) * dx;
    }
}

__global__ void zero_stats_kernel()
{
    g_sum[threadIdx.x] = 0.f;
    g_sumsq[threadIdx.x] = 0.f;
}

__global__ void bn_finalize_kernel(const float* __restrict__ gamma,
                                   const float* __restrict__ beta)
{
    const int c = threadIdx.x;
    const float n = (float)(B_ * HW_);
    const float mean = g_sum[c] / n;
    const float var  = g_sumsq[c] / n - mean * mean;
    const float inv  = rsqrtf(var + 1e-5f);
    const float sc   = inv * gamma[c];
    g_scale[c] = sc;
    g_shift[c] = beta[c] - mean * sc;
}

__global__ void normalize_kernel(float* __restrict__ out)
{
    const int i4 = blockIdx.x * blockDim.x + threadIdx.x;   // float4 index
    const int c = (i4 >> 12) & 127;                          // (4*i4 / 16384) % 128
    const float sc = g_scale[c], sh = g_shift[c];
    float4 v = ((const float4*)g_y)[i4];
    v.x = v.x * sc + sh;
    v.y = v.y * sc + sh;
    v.z = v.z * sc + sh;
    v.w = v.w * sc + sh;
    ((float4*)out)[i4] = v;
}

// ---------------------------------------------------------------------------
extern "C" void kernel_launch(void* const* d_in, const int* in_sizes, int n_in,
                              void* d_out, int out_size)
{
    const float* x      = (const float*)d_in[0];   // (8,128,128,128)
    const float* w_off  = (const float*)d_in[1];   // (256,128,3,3)
    const float* w_conv = (const float*)d_in[2];   // (128,128,3,3)
    const float* b_conv = (const float*)d_in[3];   // (128,)
    const float* gamma  = (const float*)d_in[4];   // (128,)
    const float* beta   = (const float*)d_in[5];   // (128,)
    float* out = (float*)d_out;

    void *p_off, *p_xoff, *p_y;
    cudaGetSymbolAddress(&p_off,  g_offsets);
    cudaGetSymbolAddress(&p_xoff, g_xoff);
    cudaGetSymbolAddress(&p_y,    g_y);

    zero_stats_kernel<<<1, 128>>>();

    // conv1: x -> offsets  (OC=256)
    conv3x3_kernel<256, false><<<dim3(B_ * H_, 2), 256>>>(x, w_off, nullptr, (float*)p_off);

    // deformable sampling: x, offsets -> x_off
    deform_kernel<<<B_ * C_, 256>>>(x);

    // conv2 + bias + relu + BN partial sums  (OC=128)
    conv3x3_kernel<128, true><<<dim3(B_ * H_, 1), 256>>>((const float*)p_xoff, w_conv,
                                                         b_conv, (float*)p_y);

    bn_finalize_kernel<<<1, 128>>>(gamma, beta);

    // normalize: (y - mean)*invstd*gamma + beta -> d_out
    normalize_kernel<<<(B_ * C_ * HW_ / 4) / 256, 256>>>(out);
}